// round 3
// baseline (speedup 1.0000x reference)
#include <cuda_runtime.h>
#include <cstdint>

// CustomRNN: B=64, T=512, D=U=1024
//   h = tanh(X @ W1 + b1)                      [parallel GEMM, tf32 mma]
//   y_t = h_t + tanh(y_{t-1} @ W2 + b2)        [512 sequential steps, persistent kernel]
//   out = y @ Wc + bc                          [folded into recurrence as partial dots]

#define T_STEPS 512
#define BATCH   64
#define DIM     1024
#define NCTA    128     // recurrence grid: 8 K-chunks x 16 N-chunks, all resident
#define KC_N    8
#define NC_N    16
#define KRANGE  128
#define NRANGE  64

// ---------------- device scratch (allocation-free contract) ----------------
__device__ float g_h[T_STEPS * BATCH * DIM];       // h[t][b][u], 134 MB
__device__ float g_pre[3][BATCH * DIM];            // rotating pre-activation buffers
__device__ float g_outp[T_STEPS * KC_N * BATCH];   // partial Wc dots [t][kc][b]
__device__ unsigned int g_bar;                     // monotonic grid barrier counter

// ---------------- helpers ----------------
__device__ __forceinline__ uint32_t f2tf_bits(float x) {
    uint32_t r;
    asm("cvt.rna.tf32.f32 %0, %1;" : "=r"(r) : "f"(x));
    return r;
}
__device__ __forceinline__ float f2tf(float x) { return __uint_as_float(f2tf_bits(x)); }

// tanh(x) = 1 - 2/(exp(2x)+1) via MUFU ex2/rcp. Rel err ~1e-6, saturates at +-1.
__device__ __forceinline__ float fast_tanh(float x) {
    float e, r;
    asm("ex2.approx.f32 %0, %1;" : "=f"(e) : "f"(x * 2.8853900817779268f));
    asm("rcp.approx.f32 %0, %1;" : "=f"(r) : "f"(e + 1.0f));
    return 1.0f - 2.0f * r;
}

// vectorized no-return global reduction (sm_90+): 2 floats, 8B aligned
__device__ __forceinline__ void red_add_v2(float* p, float a, float b) {
    asm volatile("red.global.add.v2.f32 [%0], {%1, %2};"
                 :: "l"(p), "f"(a), "f"(b) : "memory");
}

__device__ __forceinline__ void mma8(float c[4], uint32_t a0, uint32_t a1, uint32_t a2, uint32_t a3,
                                     uint32_t b0, uint32_t b1) {
    asm volatile(
        "mma.sync.aligned.m16n8k8.row.col.f32.tf32.tf32.f32 "
        "{%0,%1,%2,%3},{%4,%5,%6,%7},{%8,%9},{%0,%1,%2,%3};\n"
        : "+f"(c[0]), "+f"(c[1]), "+f"(c[2]), "+f"(c[3])
        : "r"(a0), "r"(a1), "r"(a2), "r"(a3), "r"(b0), "r"(b1));
}

// ---------------- init: zero pre buffers + barrier ----------------
__global__ void init_kernel() {
    int idx = blockIdx.x * blockDim.x + threadIdx.x;
    if (idx == 0) g_bar = 0u;
    if (idx < 3 * BATCH * DIM) (&g_pre[0][0])[idx] = 0.0f;
}

// ---------------- phase 1: h = tanh(X @ W1 + b1), tf32 mma -----------------
// M=32768 (b*512+t), N=1024, K=1024. 128x128 tile, BK=16, 256 threads (8 warps 2x4).
__global__ __launch_bounds__(256) void proj_kernel(const float* __restrict__ X,
                                                   const float* __restrict__ W1,
                                                   const float* __restrict__ b1) {
    __shared__ float As[2][128][20];   // [m][k] pad->20 : conflict-free frag loads
    __shared__ float Bs[2][16][136];   // [k][n] pad->136: conflict-free frag loads

    const int tid = threadIdx.x;
    const int lane = tid & 31, wid = tid >> 5;
    const int g = lane >> 2, tg = lane & 3;
    const int wm0 = (wid >> 2) * 64, wn0 = (wid & 3) * 32;
    const int mbase = blockIdx.y * 128, nbase = blockIdx.x * 128;

    const int a_row0 = tid >> 2;            // 0..63
    const int a_row1 = a_row0 + 64;         // 64..127
    const int a_kq = (tid & 3) * 4;
    const int b_row0 = tid >> 5;            // 0..7
    const int b_row1 = b_row0 + 8;          // 8..15
    const int b_nq = (tid & 31) * 4;

    float acc[4][4][4];
#pragma unroll
    for (int mt = 0; mt < 4; mt++)
#pragma unroll
        for (int nt = 0; nt < 4; nt++)
#pragma unroll
            for (int i = 0; i < 4; i++) acc[mt][nt][i] = 0.0f;

    // prologue: tile 0
    float4 ra0 = *(const float4*)&X[(mbase + a_row0) * DIM + a_kq];
    float4 ra1 = *(const float4*)&X[(mbase + a_row1) * DIM + a_kq];
    float4 rb0 = *(const float4*)&W1[b_row0 * DIM + nbase + b_nq];
    float4 rb1 = *(const float4*)&W1[b_row1 * DIM + nbase + b_nq];
    {
        float4 v;
        v.x = f2tf(ra0.x); v.y = f2tf(ra0.y); v.z = f2tf(ra0.z); v.w = f2tf(ra0.w);
        *(float4*)&As[0][a_row0][a_kq] = v;
        v.x = f2tf(ra1.x); v.y = f2tf(ra1.y); v.z = f2tf(ra1.z); v.w = f2tf(ra1.w);
        *(float4*)&As[0][a_row1][a_kq] = v;
        v.x = f2tf(rb0.x); v.y = f2tf(rb0.y); v.z = f2tf(rb0.z); v.w = f2tf(rb0.w);
        *(float4*)&Bs[0][b_row0][b_nq] = v;
        v.x = f2tf(rb1.x); v.y = f2tf(rb1.y); v.z = f2tf(rb1.z); v.w = f2tf(rb1.w);
        *(float4*)&Bs[0][b_row1][b_nq] = v;
    }
    __syncthreads();

    for (int it = 0; it < 64; ++it) {
        const int cur = it & 1;
        if (it + 1 < 64) {
            const int kk = (it + 1) * 16;
            ra0 = *(const float4*)&X[(mbase + a_row0) * DIM + kk + a_kq];
            ra1 = *(const float4*)&X[(mbase + a_row1) * DIM + kk + a_kq];
            rb0 = *(const float4*)&W1[(kk + b_row0) * DIM + nbase + b_nq];
            rb1 = *(const float4*)&W1[(kk + b_row1) * DIM + nbase + b_nq];
        }
#pragma unroll
        for (int ks = 0; ks < 2; ++ks) {
            const int k = ks * 8;
            uint32_t af[4][4], bf[4][2];
#pragma unroll
            for (int mt = 0; mt < 4; mt++) {
                const int r = wm0 + mt * 16 + g;
                af[mt][0] = __float_as_uint(As[cur][r][k + tg]);
                af[mt][1] = __float_as_uint(As[cur][r + 8][k + tg]);
                af[mt][2] = __float_as_uint(As[cur][r][k + tg + 4]);
                af[mt][3] = __float_as_uint(As[cur][r + 8][k + tg + 4]);
            }
#pragma unroll
            for (int nt = 0; nt < 4; nt++) {
                const int c = wn0 + nt * 8 + g;
                bf[nt][0] = __float_as_uint(Bs[cur][k + tg][c]);
                bf[nt][1] = __float_as_uint(Bs[cur][k + tg + 4][c]);
            }
#pragma unroll
            for (int mt = 0; mt < 4; mt++)
#pragma unroll
                for (int nt = 0; nt < 4; nt++)
                    mma8(acc[mt][nt], af[mt][0], af[mt][1], af[mt][2], af[mt][3],
                         bf[nt][0], bf[nt][1]);
        }
        __syncthreads();
        if (it + 1 < 64) {
            const int nxt = cur ^ 1;
            float4 v;
            v.x = f2tf(ra0.x); v.y = f2tf(ra0.y); v.z = f2tf(ra0.z); v.w = f2tf(ra0.w);
            *(float4*)&As[nxt][a_row0][a_kq] = v;
            v.x = f2tf(ra1.x); v.y = f2tf(ra1.y); v.z = f2tf(ra1.z); v.w = f2tf(ra1.w);
            *(float4*)&As[nxt][a_row1][a_kq] = v;
            v.x = f2tf(rb0.x); v.y = f2tf(rb0.y); v.z = f2tf(rb0.z); v.w = f2tf(rb0.w);
            *(float4*)&Bs[nxt][b_row0][b_nq] = v;
            v.x = f2tf(rb1.x); v.y = f2tf(rb1.y); v.z = f2tf(rb1.z); v.w = f2tf(rb1.w);
            *(float4*)&Bs[nxt][b_row1][b_nq] = v;
            __syncthreads();
        }
    }

    // epilogue: tanh + bias, write h[t][b][u]
#pragma unroll
    for (int nt = 0; nt < 4; nt++) {
        const int c = nbase + wn0 + nt * 8 + tg * 2;
        const float bb0 = b1[c], bb1 = b1[c + 1];
#pragma unroll
        for (int mt = 0; mt < 4; mt++) {
            const int r = mbase + wm0 + mt * 16 + g;
            {
                float2 v;
                v.x = fast_tanh(acc[mt][nt][0] + bb0);
                v.y = fast_tanh(acc[mt][nt][1] + bb1);
                const int t = r & 511, b = r >> 9;
                *(float2*)&g_h[(t * 64 + b) * DIM + c] = v;
            }
            {
                const int r2 = r + 8;
                float2 v;
                v.x = fast_tanh(acc[mt][nt][2] + bb0);
                v.y = fast_tanh(acc[mt][nt][3] + bb1);
                const int t = r2 & 511, b = r2 >> 9;
                *(float2*)&g_h[(t * 64 + b) * DIM + c] = v;
            }
        }
    }
}

// ---------------- phase 2: persistent recurrence ----------------
// Grid = 128 CTAs (kc in 0..7, nc in 0..15), 256 threads. One spin barrier/step.
// Warps 0-3: 64x64 tf32 GEMM over this CTA's 128-K slice (16 M-rows each, full K).
// Warps 4-7: folded Wc partial dot (nc==0 only) + ring-buffer zeroing.
__global__ __launch_bounds__(256, 1) void recur_kernel(const float* __restrict__ W2,
                                                       const float* __restrict__ b2,
                                                       const float* __restrict__ Wc) {
    extern __shared__ float sm[];
    float* W2s = sm;                  // [NRANGE][132], n-major, tf32-rounded
    float* ys  = sm + 64 * 132;       // [64][132]  (64 batch rows x 128 k, padded)
    float* b2s = ys + 64 * 132;       // [128]
    float* Wcs = b2s + 128;           // [128]

    const int tid = threadIdx.x, lane = tid & 31, wid = tid >> 5;
    const int g = lane >> 2, tg = lane & 3;
    const int cid = blockIdx.x;
    const int kc = cid >> 4, nc = cid & 15;
    const int kbase = kc * KRANGE, nbase = nc * NRANGE;

    // W2 slice resident in smem for all 512 steps
    for (int i = tid; i < NRANGE * KRANGE; i += 256) {
        const int n = i & 63, k = i >> 6;
        W2s[n * 132 + k] = f2tf(W2[(kbase + k) * DIM + nbase + n]);
    }
    if (tid < 128) { b2s[tid] = b2[kbase + tid]; Wcs[tid] = Wc[kbase + tid]; }
    __syncthreads();

    for (int t = 0; t < T_STEPS; ++t) {
        const float* pre = g_pre[t % 3];
        float* nxt = g_pre[(t + 1) % 3];
        float* zb  = g_pre[(t + 2) % 3];
        const float* hrow = g_h + (size_t)t * BATCH * DIM;

        // build y slice: y[b][k] = h_t[b][k] + tanh(pre[b][k] + b2[k]), tf32-rounded
        for (int q = tid; q < 64 * 32; q += 256) {
            const int b = q >> 5, kq = (q & 31) * 4;
            const float4 p = *(const float4*)&pre[b * DIM + kbase + kq];
            const float4 h4 = *(const float4*)&hrow[b * DIM + kbase + kq];
            float4 y;
            y.x = f2tf(h4.x + fast_tanh(p.x + b2s[kq + 0]));
            y.y = f2tf(h4.y + fast_tanh(p.y + b2s[kq + 1]));
            y.z = f2tf(h4.z + fast_tanh(p.z + b2s[kq + 2]));
            y.w = f2tf(h4.w + fast_tanh(p.w + b2s[kq + 3]));
            *(float4*)&ys[b * 132 + kq] = y;
        }
        __syncthreads();

        if (wid < 4) {
            // GEMM partial: 64(M) x 64(N) x 128(K), warp w owns rows [w*16, w*16+16)
            const int m0 = wid * 16;
            float acc[8][4];
#pragma unroll
            for (int nt = 0; nt < 8; nt++)
#pragma unroll
                for (int i = 0; i < 4; i++) acc[nt][i] = 0.0f;

#pragma unroll
            for (int ks = 0; ks < 16; ++ks) {
                const int k = ks * 8;
                const uint32_t a0 = __float_as_uint(ys[(m0 + g) * 132 + k + tg]);
                const uint32_t a1 = __float_as_uint(ys[(m0 + g + 8) * 132 + k + tg]);
                const uint32_t a2 = __float_as_uint(ys[(m0 + g) * 132 + k + tg + 4]);
                const uint32_t a3 = __float_as_uint(ys[(m0 + g + 8) * 132 + k + tg + 4]);
#pragma unroll
                for (int nt = 0; nt < 8; ++nt) {
                    const uint32_t b0 = __float_as_uint(W2s[(nt * 8 + g) * 132 + k + tg]);
                    const uint32_t b1v = __float_as_uint(W2s[(nt * 8 + g) * 132 + k + tg + 4]);
                    mma8(acc[nt], a0, a1, a2, a3, b0, b1v);
                }
            }

            // accumulate partials into next pre buffer (vectorized no-return RED)
#pragma unroll
            for (int nt = 0; nt < 8; ++nt) {
                const int ccol = nbase + nt * 8 + tg * 2;
                const int r = m0 + g;
                red_add_v2(&nxt[r * DIM + ccol],       acc[nt][0], acc[nt][1]);
                red_add_v2(&nxt[(r + 8) * DIM + ccol], acc[nt][2], acc[nt][3]);
            }
        } else {
            const int ut = tid - 128;   // 0..127
            // folded output projection: partial dot with Wc (deterministic stores)
            if (nc == 0) {
                const int r = ut >> 1, half = ut & 1;   // row 0..63, 2 threads/row
                float s = 0.0f;
#pragma unroll 16
                for (int k = half * 64; k < half * 64 + 64; ++k) s += ys[r * 132 + k] * Wcs[k];
                s += __shfl_xor_sync(0xffffffffu, s, 1);
                if (half == 0) g_outp[t * (KC_N * BATCH) + kc * BATCH + r] = s;
            }
            // zero the buffer that becomes the accumulation target at step t+1
            ((float4*)zb)[cid * 128 + ut] = make_float4(0.f, 0.f, 0.f, 0.f);
        }

        // grid barrier (monotonic counter; all 128 CTAs resident)
        __syncthreads();
        if (tid == 0) {
            __threadfence();
            atomicAdd(&g_bar, 1u);
            const unsigned target = (unsigned)(t + 1) * NCTA;
            while (*((volatile unsigned int*)&g_bar) < target) { }
            __threadfence();
        }
        __syncthreads();
    }
}

// ---------------- phase 3: reduce Wc partials ----------------
__global__ void final_kernel(const float* __restrict__ bc, float* __restrict__ out) {
    const int idx = blockIdx.x * blockDim.x + threadIdx.x;
    if (idx < BATCH * T_STEPS) {
        const int b = idx >> 9, t = idx & 511;
        float s = bc[0];
#pragma unroll
        for (int kc = 0; kc < KC_N; kc++) s += g_outp[t * (KC_N * BATCH) + kc * BATCH + b];
        out[idx] = s;   // out[b][t][0], idx = b*512 + t
    }
}

// ---------------- launch ----------------
extern "C" void kernel_launch(void* const* d_in, const int* in_sizes, int n_in,
                              void* d_out, int out_size) {
    const float* X  = (const float*)d_in[0];
    const float* W1 = (const float*)d_in[1];
    const float* b1 = (const float*)d_in[2];
    const float* W2 = (const float*)d_in[3];
    const float* b2 = (const float*)d_in[4];
    const float* Wc = (const float*)d_in[5];
    const float* bc = (const float*)d_in[6];
    float* out = (float*)d_out;

    const int recur_smem = (64 * 132 + 64 * 132 + 128 + 128) * 4;  // 68608 B
    cudaFuncSetAttribute(recur_kernel, cudaFuncAttributeMaxDynamicSharedMemorySize, recur_smem);

    init_kernel<<<768, 256>>>();
    proj_kernel<<<dim3(8, 256), 256>>>(X, W1, b1);
    recur_kernel<<<NCTA, 256, recur_smem>>>(W2, b2, Wc);
    final_kernel<<<128, 256>>>(bc, out);
}

// round 4
// speedup vs baseline: 1.0244x; 1.0244x over previous
#include <cuda_runtime.h>
#include <cstdint>

// CustomRNN: B=64, T=512, D=U=1024
//   h = tanh(X @ W1 + b1)                      [parallel GEMM, tf32 mma]
//   y_t = h_t + tanh(y_{t-1} @ W2 + b2)        [512 sequential steps, persistent kernel]
//   out = y @ Wc + bc                          [folded into recurrence as partial dots]

#define T_STEPS 512
#define BATCH   64
#define DIM     1024
#define NCTA    128     // recurrence grid: 8 K-chunks x 16 N-chunks, all resident
#define KC_N    8
#define NC_N    16
#define KRANGE  128
#define NRANGE  64

// ---------------- device scratch (allocation-free contract) ----------------
__device__ float g_h[T_STEPS * BATCH * DIM];       // h[t][b][u], 134 MB
__device__ float g_pre[3][BATCH * DIM];            // rotating pre-activation buffers
__device__ float g_outp[T_STEPS * KC_N * BATCH];   // partial Wc dots [t][kc][b]
__device__ unsigned int g_bar;                     // monotonic grid barrier counter

// ---------------- helpers ----------------
__device__ __forceinline__ uint32_t f2tf_bits(float x) {
    uint32_t r;
    asm("cvt.rna.tf32.f32 %0, %1;" : "=r"(r) : "f"(x));
    return r;
}
__device__ __forceinline__ float f2tf(float x) { return __uint_as_float(f2tf_bits(x)); }

// tanh(x) = 1 - 2/(exp(2x)+1) via MUFU ex2/rcp. Rel err ~1e-6, saturates at +-1.
__device__ __forceinline__ float fast_tanh(float x) {
    float e, r;
    asm("ex2.approx.f32 %0, %1;" : "=f"(e) : "f"(x * 2.8853900817779268f));
    asm("rcp.approx.f32 %0, %1;" : "=f"(r) : "f"(e + 1.0f));
    return 1.0f - 2.0f * r;
}

// vectorized no-return global float4 reduction (sm_90+)
__device__ __forceinline__ void red_add_v4(float* p, float4 v) {
    asm volatile("red.global.add.v4.f32 [%0], {%1, %2, %3, %4};"
                 :: "l"(p), "f"(v.x), "f"(v.y), "f"(v.z), "f"(v.w) : "memory");
}

__device__ __forceinline__ void mma8(float c[4], uint32_t a0, uint32_t a1, uint32_t a2, uint32_t a3,
                                     uint32_t b0, uint32_t b1) {
    asm volatile(
        "mma.sync.aligned.m16n8k8.row.col.f32.tf32.tf32.f32 "
        "{%0,%1,%2,%3},{%4,%5,%6,%7},{%8,%9},{%0,%1,%2,%3};\n"
        : "+f"(c[0]), "+f"(c[1]), "+f"(c[2]), "+f"(c[3])
        : "r"(a0), "r"(a1), "r"(a2), "r"(a3), "r"(b0), "r"(b1));
}

// ---------------- init: zero pre buffers + barrier ----------------
__global__ void init_kernel() {
    int idx = blockIdx.x * blockDim.x + threadIdx.x;
    if (idx == 0) g_bar = 0u;
    if (idx < 3 * BATCH * DIM) (&g_pre[0][0])[idx] = 0.0f;
}

// ---------------- phase 1: h = tanh(X @ W1 + b1), tf32 mma -----------------
// M=32768 (b*512+t), N=1024, K=1024. 128x128 tile, BK=16, 256 threads (8 warps 2x4).
__global__ __launch_bounds__(256) void proj_kernel(const float* __restrict__ X,
                                                   const float* __restrict__ W1,
                                                   const float* __restrict__ b1) {
    __shared__ float As[2][128][20];   // [m][k] pad->20 : conflict-free frag loads
    __shared__ float Bs[2][16][136];   // [k][n] pad->136: conflict-free frag loads

    const int tid = threadIdx.x;
    const int lane = tid & 31, wid = tid >> 5;
    const int g = lane >> 2, tg = lane & 3;
    const int wm0 = (wid >> 2) * 64, wn0 = (wid & 3) * 32;
    const int mbase = blockIdx.y * 128, nbase = blockIdx.x * 128;

    const int a_row0 = tid >> 2;            // 0..63
    const int a_row1 = a_row0 + 64;         // 64..127
    const int a_kq = (tid & 3) * 4;
    const int b_row0 = tid >> 5;            // 0..7
    const int b_row1 = b_row0 + 8;          // 8..15
    const int b_nq = (tid & 31) * 4;

    float acc[4][4][4];
#pragma unroll
    for (int mt = 0; mt < 4; mt++)
#pragma unroll
        for (int nt = 0; nt < 4; nt++)
#pragma unroll
            for (int i = 0; i < 4; i++) acc[mt][nt][i] = 0.0f;

    // prologue: tile 0
    float4 ra0 = *(const float4*)&X[(mbase + a_row0) * DIM + a_kq];
    float4 ra1 = *(const float4*)&X[(mbase + a_row1) * DIM + a_kq];
    float4 rb0 = *(const float4*)&W1[b_row0 * DIM + nbase + b_nq];
    float4 rb1 = *(const float4*)&W1[b_row1 * DIM + nbase + b_nq];
    {
        float4 v;
        v.x = f2tf(ra0.x); v.y = f2tf(ra0.y); v.z = f2tf(ra0.z); v.w = f2tf(ra0.w);
        *(float4*)&As[0][a_row0][a_kq] = v;
        v.x = f2tf(ra1.x); v.y = f2tf(ra1.y); v.z = f2tf(ra1.z); v.w = f2tf(ra1.w);
        *(float4*)&As[0][a_row1][a_kq] = v;
        v.x = f2tf(rb0.x); v.y = f2tf(rb0.y); v.z = f2tf(rb0.z); v.w = f2tf(rb0.w);
        *(float4*)&Bs[0][b_row0][b_nq] = v;
        v.x = f2tf(rb1.x); v.y = f2tf(rb1.y); v.z = f2tf(rb1.z); v.w = f2tf(rb1.w);
        *(float4*)&Bs[0][b_row1][b_nq] = v;
    }
    __syncthreads();

    for (int it = 0; it < 64; ++it) {
        const int cur = it & 1;
        if (it + 1 < 64) {
            const int kk = (it + 1) * 16;
            ra0 = *(const float4*)&X[(mbase + a_row0) * DIM + kk + a_kq];
            ra1 = *(const float4*)&X[(mbase + a_row1) * DIM + kk + a_kq];
            rb0 = *(const float4*)&W1[(kk + b_row0) * DIM + nbase + b_nq];
            rb1 = *(const float4*)&W1[(kk + b_row1) * DIM + nbase + b_nq];
        }
#pragma unroll
        for (int ks = 0; ks < 2; ++ks) {
            const int k = ks * 8;
            uint32_t af[4][4], bf[4][2];
#pragma unroll
            for (int mt = 0; mt < 4; mt++) {
                const int r = wm0 + mt * 16 + g;
                af[mt][0] = __float_as_uint(As[cur][r][k + tg]);
                af[mt][1] = __float_as_uint(As[cur][r + 8][k + tg]);
                af[mt][2] = __float_as_uint(As[cur][r][k + tg + 4]);
                af[mt][3] = __float_as_uint(As[cur][r + 8][k + tg + 4]);
            }
#pragma unroll
            for (int nt = 0; nt < 4; nt++) {
                const int c = wn0 + nt * 8 + g;
                bf[nt][0] = __float_as_uint(Bs[cur][k + tg][c]);
                bf[nt][1] = __float_as_uint(Bs[cur][k + tg + 4][c]);
            }
#pragma unroll
            for (int mt = 0; mt < 4; mt++)
#pragma unroll
                for (int nt = 0; nt < 4; nt++)
                    mma8(acc[mt][nt], af[mt][0], af[mt][1], af[mt][2], af[mt][3],
                         bf[nt][0], bf[nt][1]);
        }
        __syncthreads();
        if (it + 1 < 64) {
            const int nxt = cur ^ 1;
            float4 v;
            v.x = f2tf(ra0.x); v.y = f2tf(ra0.y); v.z = f2tf(ra0.z); v.w = f2tf(ra0.w);
            *(float4*)&As[nxt][a_row0][a_kq] = v;
            v.x = f2tf(ra1.x); v.y = f2tf(ra1.y); v.z = f2tf(ra1.z); v.w = f2tf(ra1.w);
            *(float4*)&As[nxt][a_row1][a_kq] = v;
            v.x = f2tf(rb0.x); v.y = f2tf(rb0.y); v.z = f2tf(rb0.z); v.w = f2tf(rb0.w);
            *(float4*)&Bs[nxt][b_row0][b_nq] = v;
            v.x = f2tf(rb1.x); v.y = f2tf(rb1.y); v.z = f2tf(rb1.z); v.w = f2tf(rb1.w);
            *(float4*)&Bs[nxt][b_row1][b_nq] = v;
            __syncthreads();
        }
    }

    // epilogue: tanh + bias, write h[t][b][u]
#pragma unroll
    for (int nt = 0; nt < 4; nt++) {
        const int c = nbase + wn0 + nt * 8 + tg * 2;
        const float bb0 = b1[c], bb1 = b1[c + 1];
#pragma unroll
        for (int mt = 0; mt < 4; mt++) {
            const int r = mbase + wm0 + mt * 16 + g;
            {
                float2 v;
                v.x = fast_tanh(acc[mt][nt][0] + bb0);
                v.y = fast_tanh(acc[mt][nt][1] + bb1);
                const int t = r & 511, b = r >> 9;
                *(float2*)&g_h[(t * 64 + b) * DIM + c] = v;
            }
            {
                const int r2 = r + 8;
                float2 v;
                v.x = fast_tanh(acc[mt][nt][2] + bb0);
                v.y = fast_tanh(acc[mt][nt][3] + bb1);
                const int t = r2 & 511, b = r2 >> 9;
                *(float2*)&g_h[(t * 64 + b) * DIM + c] = v;
            }
        }
    }
}

// ---------------- phase 2: persistent recurrence ----------------
// Grid = 128 CTAs (kc 0..7, nc 0..15), 256 threads, 1 CTA/SM. One spin barrier/step.
// Phase a: all threads build y slice (smem)
// Phase b: ALL 8 warps GEMM 64x64x128 (warp grid 4M x 2N), stage accs in smem
// Phase c: coalesced red.v4 of staged accs + Wc partial dot + ring zeroing
__global__ __launch_bounds__(256, 1) void recur_kernel(const float* __restrict__ W2,
                                                       const float* __restrict__ b2,
                                                       const float* __restrict__ Wc) {
    extern __shared__ float sm[];
    float* W2s  = sm;                    // [64][132], n-major, tf32-rounded
    float* ys   = sm + 64 * 132;         // [64][132]
    float* accs = ys + 64 * 132;         // [64][68]  staged GEMM partials
    float* b2s  = accs + 64 * 68;        // [128]
    float* Wcs  = b2s + 128;             // [128]

    const int tid = threadIdx.x, lane = tid & 31, wid = tid >> 5;
    const int g = lane >> 2, tg = lane & 3;
    const int cid = blockIdx.x;
    const int kc = cid >> 4, nc = cid & 15;
    const int kbase = kc * KRANGE, nbase = nc * NRANGE;

    // W2 slice resident in smem for all 512 steps
    for (int i = tid; i < NRANGE * KRANGE; i += 256) {
        const int n = i & 63, k = i >> 6;
        W2s[n * 132 + k] = f2tf(W2[(kbase + k) * DIM + nbase + n]);
    }
    if (tid < 128) { b2s[tid] = b2[kbase + tid]; Wcs[tid] = Wc[kbase + tid]; }
    __syncthreads();

    const int wm0 = (wid >> 1) * 16;     // 0,16,32,48
    const int wn0 = (wid & 1) * 32;      // 0,32

    for (int t = 0; t < T_STEPS; ++t) {
        const float* pre = g_pre[t % 3];
        float* nxt = g_pre[(t + 1) % 3];
        float* zb  = g_pre[(t + 2) % 3];
        const float* hrow = g_h + (size_t)t * BATCH * DIM;

        // (a) y[b][k] = h_t[b][k] + tanh(pre[b][k] + b2[k]), tf32-rounded
        for (int q = tid; q < 64 * 32; q += 256) {
            const int b = q >> 5, kq = (q & 31) * 4;
            const float4 p = *(const float4*)&pre[b * DIM + kbase + kq];
            const float4 h4 = *(const float4*)&hrow[b * DIM + kbase + kq];
            float4 y;
            y.x = f2tf(h4.x + fast_tanh(p.x + b2s[kq + 0]));
            y.y = f2tf(h4.y + fast_tanh(p.y + b2s[kq + 1]));
            y.z = f2tf(h4.z + fast_tanh(p.z + b2s[kq + 2]));
            y.w = f2tf(h4.w + fast_tanh(p.w + b2s[kq + 3]));
            *(float4*)&ys[b * 132 + kq] = y;
        }
        __syncthreads();

        // (b) GEMM partial: warp tile 16(M) x 32(N), full 128-K slice
        {
            float acc[4][4];
#pragma unroll
            for (int nt = 0; nt < 4; nt++)
#pragma unroll
                for (int i = 0; i < 4; i++) acc[nt][i] = 0.0f;

#pragma unroll
            for (int ks = 0; ks < 16; ++ks) {
                const int k = ks * 8;
                const uint32_t a0 = __float_as_uint(ys[(wm0 + g) * 132 + k + tg]);
                const uint32_t a1 = __float_as_uint(ys[(wm0 + g + 8) * 132 + k + tg]);
                const uint32_t a2 = __float_as_uint(ys[(wm0 + g) * 132 + k + tg + 4]);
                const uint32_t a3 = __float_as_uint(ys[(wm0 + g + 8) * 132 + k + tg + 4]);
#pragma unroll
                for (int nt = 0; nt < 4; ++nt) {
                    const int col = wn0 + nt * 8 + g;
                    const uint32_t b0 = __float_as_uint(W2s[col * 132 + k + tg]);
                    const uint32_t b1v = __float_as_uint(W2s[col * 132 + k + tg + 4]);
                    mma8(acc[nt], a0, a1, a2, a3, b0, b1v);
                }
            }
            // stage into smem for coalesced vectorized reduction
#pragma unroll
            for (int nt = 0; nt < 4; ++nt) {
                const int col = wn0 + nt * 8 + tg * 2;
                *(float2*)&accs[(wm0 + g) * 68 + col]     = make_float2(acc[nt][0], acc[nt][1]);
                *(float2*)&accs[(wm0 + g + 8) * 68 + col] = make_float2(acc[nt][2], acc[nt][3]);
            }
        }
        __syncthreads();

        // (c) vectorized reductions + Wc dot + ring zeroing
        {
            const int b = tid >> 2, j = tid & 3;   // 4 threads per batch row
#pragma unroll
            for (int i = 0; i < 4; ++i) {
                const int col = (j + 4 * i) * 4;   // 0..60, float4 aligned
                const float4 v = *(const float4*)&accs[b * 68 + col];
                red_add_v4(&nxt[b * DIM + nbase + col], v);
            }
        }
        if (nc == 0 && tid < 128) {
            // folded output projection: partial dot with Wc over this 128-K slice
            const int r = tid >> 1, half = tid & 1;
            float s = 0.0f;
#pragma unroll 16
            for (int k = half * 64; k < half * 64 + 64; ++k) s += ys[r * 132 + k] * Wcs[k];
            s += __shfl_xor_sync(0xffffffffu, s, 1);
            if (half == 0) g_outp[t * (KC_N * BATCH) + kc * BATCH + r] = s;
        }
        if (tid >= 128) {
            // zero the buffer that becomes the accumulation target at step t+1
            ((float4*)zb)[cid * 128 + (tid - 128)] = make_float4(0.f, 0.f, 0.f, 0.f);
        }

        // grid barrier (monotonic counter; all 128 CTAs resident).
        // every thread fences so its RED/ST ops are globally visible pre-arrival.
        __threadfence();
        __syncthreads();
        if (tid == 0) {
            atomicAdd(&g_bar, 1u);
            const unsigned target = (unsigned)(t + 1) * NCTA;
            while (*((volatile unsigned int*)&g_bar) < target) { }
        }
        __syncthreads();
    }
}

// ---------------- phase 3: reduce Wc partials ----------------
__global__ void final_kernel(const float* __restrict__ bc, float* __restrict__ out) {
    const int idx = blockIdx.x * blockDim.x + threadIdx.x;
    if (idx < BATCH * T_STEPS) {
        const int b = idx >> 9, t = idx & 511;
        float s = bc[0];
#pragma unroll
        for (int kc = 0; kc < KC_N; kc++) s += g_outp[t * (KC_N * BATCH) + kc * BATCH + b];
        out[idx] = s;   // out[b][t][0], idx = b*512 + t
    }
}

// ---------------- launch ----------------
extern "C" void kernel_launch(void* const* d_in, const int* in_sizes, int n_in,
                              void* d_out, int out_size) {
    const float* X  = (const float*)d_in[0];
    const float* W1 = (const float*)d_in[1];
    const float* b1 = (const float*)d_in[2];
    const float* W2 = (const float*)d_in[3];
    const float* b2 = (const float*)d_in[4];
    const float* Wc = (const float*)d_in[5];
    const float* bc = (const float*)d_in[6];
    float* out = (float*)d_out;

    const int recur_smem = (64 * 132 + 64 * 132 + 64 * 68 + 128 + 128) * 4;  // 86016 B
    cudaFuncSetAttribute(recur_kernel, cudaFuncAttributeMaxDynamicSharedMemorySize, recur_smem);

    init_kernel<<<768, 256>>>();
    proj_kernel<<<dim3(8, 256), 256>>>(X, W1, b1);
    recur_kernel<<<NCTA, 256, recur_smem>>>(W2, b2, Wc);
    final_kernel<<<128, 256>>>(bc, out);
}

// round 6
// speedup vs baseline: 1.1469x; 1.1196x over previous
#include <cuda_runtime.h>
#include <cstdint>

// CustomRNN: B=64, T=512, D=U=1024
//   h = tanh(X @ W1 + b1)                      [parallel GEMM, tf32 mma]
//   y_t = h_t + tanh(y_{t-1} @ W2 + b2)        [512 sequential steps, persistent kernel]
//   out = y @ Wc + bc                          [folded into recurrence]

#define T_STEPS 512
#define BATCH   64
#define DIM     1024
#define NCTA    128     // recurrence grid: 8 K-chunks x 16 N-chunks, all resident
#define KC_N    8
#define KRANGE  128
#define NRANGE  64

// ---------------- device scratch (allocation-free contract) ----------------
__device__ float g_h[T_STEPS * BATCH * DIM];       // h[t][b][u], 134 MB
__device__ float g_pre[3][BATCH * DIM];            // rotating pre-activation buffers
__device__ float g_outp[T_STEPS * KC_N * BATCH];   // partial Wc dots [t][kc][b]
__device__ unsigned int g_bar;                     // monotonic grid barrier counter

// ---------------- helpers ----------------
__device__ __forceinline__ uint32_t f2tf_bits(float x) {
    uint32_t r;
    asm("cvt.rna.tf32.f32 %0, %1;" : "=r"(r) : "f"(x));
    return r;
}
__device__ __forceinline__ float f2tf(float x) { return __uint_as_float(f2tf_bits(x)); }

// tanh(x) = 1 - 2/(exp(2x)+1) via MUFU ex2/rcp. Rel err ~1e-6, saturates at +-1.
__device__ __forceinline__ float fast_tanh(float x) {
    float e, r;
    asm("ex2.approx.f32 %0, %1;" : "=f"(e) : "f"(x * 2.8853900817779268f));
    asm("rcp.approx.f32 %0, %1;" : "=f"(r) : "f"(e + 1.0f));
    return 1.0f - 2.0f * r;
}

// vectorized no-return global float2 reduction (sm_90+)
__device__ __forceinline__ void red_add_v2(float* p, float a, float b) {
    asm volatile("red.global.add.v2.f32 [%0], {%1, %2};"
                 :: "l"(p), "f"(a), "f"(b) : "memory");
}

__device__ __forceinline__ void mma8(float c[4], uint32_t a0, uint32_t a1, uint32_t a2, uint32_t a3,
                                     uint32_t b0, uint32_t b1) {
    asm volatile(
        "mma.sync.aligned.m16n8k8.row.col.f32.tf32.tf32.f32 "
        "{%0,%1,%2,%3},{%4,%5,%6,%7},{%8,%9},{%0,%1,%2,%3};\n"
        : "+f"(c[0]), "+f"(c[1]), "+f"(c[2]), "+f"(c[3])
        : "r"(a0), "r"(a1), "r"(a2), "r"(a3), "r"(b0), "r"(b1));
}

__device__ __forceinline__ void pair_bar(int id) {
    asm volatile("bar.sync %0, 64;" :: "r"(id) : "memory");
}

// ---------------- phase 1: h = tanh(X @ W1 + b1), tf32 mma -----------------
// M=32768 (b*512+t), N=1024, K=1024. 128x128 tile, BK=16, 256 threads (8 warps 2x4).
// Also performs per-run init (zero pre buffers + barrier counter).
__global__ __launch_bounds__(256) void proj_kernel(const float* __restrict__ X,
                                                   const float* __restrict__ W1,
                                                   const float* __restrict__ b1) {
    __shared__ float As[2][128][20];   // [m][k] pad->20 : conflict-free frag loads
    __shared__ float Bs[2][16][136];   // [k][n] pad->136: conflict-free frag loads

    const int tid = threadIdx.x;
    // folded init: zero g_pre (3 buffers) + g_bar before recur launches
    {
        const int flat = (blockIdx.y * gridDim.x + blockIdx.x) * 256 + tid;
        if (flat < 3 * BATCH * DIM / 4)
            ((float4*)&g_pre[0][0])[flat] = make_float4(0.f, 0.f, 0.f, 0.f);
        if (flat == 0) g_bar = 0u;
    }

    const int lane = tid & 31, wid = tid >> 5;
    const int g = lane >> 2, tg = lane & 3;
    const int wm0 = (wid >> 2) * 64, wn0 = (wid & 3) * 32;
    const int mbase = blockIdx.y * 128, nbase = blockIdx.x * 128;

    const int a_row0 = tid >> 2;            // 0..63
    const int a_row1 = a_row0 + 64;         // 64..127
    const int a_kq = (tid & 3) * 4;
    const int b_row0 = tid >> 5;            // 0..7
    const int b_row1 = b_row0 + 8;          // 8..15
    const int b_nq = (tid & 31) * 4;

    float acc[4][4][4];
#pragma unroll
    for (int mt = 0; mt < 4; mt++)
#pragma unroll
        for (int nt = 0; nt < 4; nt++)
#pragma unroll
            for (int i = 0; i < 4; i++) acc[mt][nt][i] = 0.0f;

    // prologue: tile 0
    float4 ra0 = *(const float4*)&X[(mbase + a_row0) * DIM + a_kq];
    float4 ra1 = *(const float4*)&X[(mbase + a_row1) * DIM + a_kq];
    float4 rb0 = *(const float4*)&W1[b_row0 * DIM + nbase + b_nq];
    float4 rb1 = *(const float4*)&W1[b_row1 * DIM + nbase + b_nq];
    {
        float4 v;
        v.x = f2tf(ra0.x); v.y = f2tf(ra0.y); v.z = f2tf(ra0.z); v.w = f2tf(ra0.w);
        *(float4*)&As[0][a_row0][a_kq] = v;
        v.x = f2tf(ra1.x); v.y = f2tf(ra1.y); v.z = f2tf(ra1.z); v.w = f2tf(ra1.w);
        *(float4*)&As[0][a_row1][a_kq] = v;
        v.x = f2tf(rb0.x); v.y = f2tf(rb0.y); v.z = f2tf(rb0.z); v.w = f2tf(rb0.w);
        *(float4*)&Bs[0][b_row0][b_nq] = v;
        v.x = f2tf(rb1.x); v.y = f2tf(rb1.y); v.z = f2tf(rb1.z); v.w = f2tf(rb1.w);
        *(float4*)&Bs[0][b_row1][b_nq] = v;
    }
    __syncthreads();

    for (int it = 0; it < 64; ++it) {
        const int cur = it & 1;
        if (it + 1 < 64) {
            const int kk = (it + 1) * 16;
            ra0 = *(const float4*)&X[(mbase + a_row0) * DIM + kk + a_kq];
            ra1 = *(const float4*)&X[(mbase + a_row1) * DIM + kk + a_kq];
            rb0 = *(const float4*)&W1[(kk + b_row0) * DIM + nbase + b_nq];
            rb1 = *(const float4*)&W1[(kk + b_row1) * DIM + nbase + b_nq];
        }
#pragma unroll
        for (int ks = 0; ks < 2; ++ks) {
            const int k = ks * 8;
            uint32_t af[4][4], bf[4][2];
#pragma unroll
            for (int mt = 0; mt < 4; mt++) {
                const int r = wm0 + mt * 16 + g;
                af[mt][0] = __float_as_uint(As[cur][r][k + tg]);
                af[mt][1] = __float_as_uint(As[cur][r + 8][k + tg]);
                af[mt][2] = __float_as_uint(As[cur][r][k + tg + 4]);
                af[mt][3] = __float_as_uint(As[cur][r + 8][k + tg + 4]);
            }
#pragma unroll
            for (int nt = 0; nt < 4; nt++) {
                const int c = wn0 + nt * 8 + g;
                bf[nt][0] = __float_as_uint(Bs[cur][k + tg][c]);
                bf[nt][1] = __float_as_uint(Bs[cur][k + tg + 4][c]);
            }
#pragma unroll
            for (int mt = 0; mt < 4; mt++)
#pragma unroll
                for (int nt = 0; nt < 4; nt++)
                    mma8(acc[mt][nt], af[mt][0], af[mt][1], af[mt][2], af[mt][3],
                         bf[nt][0], bf[nt][1]);
        }
        __syncthreads();
        if (it + 1 < 64) {
            const int nxt = cur ^ 1;
            float4 v;
            v.x = f2tf(ra0.x); v.y = f2tf(ra0.y); v.z = f2tf(ra0.z); v.w = f2tf(ra0.w);
            *(float4*)&As[nxt][a_row0][a_kq] = v;
            v.x = f2tf(ra1.x); v.y = f2tf(ra1.y); v.z = f2tf(ra1.z); v.w = f2tf(ra1.w);
            *(float4*)&As[nxt][a_row1][a_kq] = v;
            v.x = f2tf(rb0.x); v.y = f2tf(rb0.y); v.z = f2tf(rb0.z); v.w = f2tf(rb0.w);
            *(float4*)&Bs[nxt][b_row0][b_nq] = v;
            v.x = f2tf(rb1.x); v.y = f2tf(rb1.y); v.z = f2tf(rb1.z); v.w = f2tf(rb1.w);
            *(float4*)&Bs[nxt][b_row1][b_nq] = v;
            __syncthreads();
        }
    }

    // epilogue: tanh + bias, write h[t][b][u]
#pragma unroll
    for (int nt = 0; nt < 4; nt++) {
        const int c = nbase + wn0 + nt * 8 + tg * 2;
        const float bb0 = b1[c], bb1 = b1[c + 1];
#pragma unroll
        for (int mt = 0; mt < 4; mt++) {
            const int r = mbase + wm0 + mt * 16 + g;
            {
                float2 v;
                v.x = fast_tanh(acc[mt][nt][0] + bb0);
                v.y = fast_tanh(acc[mt][nt][1] + bb1);
                const int t = r & 511, b = r >> 9;
                *(float2*)&g_h[(t * 64 + b) * DIM + c] = v;
            }
            {
                const int r2 = r + 8;
                float2 v;
                v.x = fast_tanh(acc[mt][nt][2] + bb0);
                v.y = fast_tanh(acc[mt][nt][3] + bb1);
                const int t = r2 & 511, b = r2 >> 9;
                *(float2*)&g_h[(t * 64 + b) * DIM + c] = v;
            }
        }
    }
}

// ---------------- phase 2: persistent recurrence ----------------
// Grid = 128 CTAs (kc 0..7, nc 0..15), 256 threads = 4 warp pairs.
// Warp pair p owns M-rows [16p,16p+16): each warp builds 8 y-rows, pair-syncs
// (named barrier, 64 threads), then GEMMs its 16x32 tile over the 128-K slice.
// h for step t+1 is prefetched into registers BEFORE the grid barrier.
// Epilogue: CTAs 0..31 reduce Wc partials into the output (folded final).
__global__ __launch_bounds__(256, 1) void recur_kernel(const float* __restrict__ W2,
                                                       const float* __restrict__ b2,
                                                       const float* __restrict__ Wc,
                                                       const float* __restrict__ bc,
                                                       float* __restrict__ out) {
    extern __shared__ float sm[];
    float* W2s = sm;                  // [64][132], n-major, tf32-rounded
    float* ys  = sm + 64 * 132;       // [64][132]
    float* b2s = ys + 64 * 132;       // [128]
    float* Wcs = b2s + 128;           // [128]

    const int tid = threadIdx.x, lane = tid & 31, wid = tid >> 5;
    const int g = lane >> 2, tg = lane & 3;
    const int pair = wid >> 1, sub = wid & 1;
    const int m0 = pair * 16, n0 = sub * 32;
    const int rb0 = pair * 16 + sub * 8;     // this warp builds rows rb0..rb0+7
    const int cid = blockIdx.x;
    const int kc = cid >> 4, nc = cid & 15;
    const int kbase = kc * KRANGE, nbase = nc * NRANGE;

    // W2 slice resident in smem for all 512 steps
    for (int i = tid; i < NRANGE * KRANGE; i += 256) {
        const int n = i & 63, k = i >> 6;
        W2s[n * 132 + k] = f2tf(W2[(kbase + k) * DIM + nbase + n]);
    }
    if (tid < 128) { b2s[tid] = b2[kbase + tid]; Wcs[tid] = Wc[kbase + tid]; }
    __syncthreads();

    // prologue: prefetch h rows for t=0 (row = batch index, cols = K slice)
    float4 hreg[8];
#pragma unroll
    for (int j = 0; j < 8; ++j)
        hreg[j] = *(const float4*)&g_h[(size_t)(rb0 + j) * DIM + kbase + lane * 4];

    for (int t = 0; t < T_STEPS; ++t) {
        const float* pre = g_pre[t % 3];
        float* nxt = g_pre[(t + 1) % 3];
        float* zb  = g_pre[(t + 2) % 3];

        // (a) build own 8 y rows: y = tf32(h + tanh(pre + b2))
        float4 preg[8];
#pragma unroll
        for (int j = 0; j < 8; ++j)
            preg[j] = *(const float4*)&pre[(rb0 + j) * DIM + kbase + lane * 4];
#pragma unroll
        for (int j = 0; j < 8; ++j) {
            float4 y;
            y.x = f2tf(hreg[j].x + fast_tanh(preg[j].x + b2s[lane * 4 + 0]));
            y.y = f2tf(hreg[j].y + fast_tanh(preg[j].y + b2s[lane * 4 + 1]));
            y.z = f2tf(hreg[j].z + fast_tanh(preg[j].z + b2s[lane * 4 + 2]));
            y.w = f2tf(hreg[j].w + fast_tanh(preg[j].w + b2s[lane * 4 + 3]));
            *(float4*)&ys[(rb0 + j) * 132 + lane * 4] = y;
        }
        pair_bar(pair + 1);   // sync the 2 warps sharing rows [m0, m0+16)

        // (b) GEMM: warp tile 16(M) x 32(N) x 128(K)
        float acc[4][4];
#pragma unroll
        for (int nt = 0; nt < 4; nt++)
#pragma unroll
            for (int i = 0; i < 4; i++) acc[nt][i] = 0.0f;

#pragma unroll
        for (int ks = 0; ks < 16; ++ks) {
            const int k = ks * 8;
            const uint32_t a0 = __float_as_uint(ys[(m0 + g) * 132 + k + tg]);
            const uint32_t a1 = __float_as_uint(ys[(m0 + g + 8) * 132 + k + tg]);
            const uint32_t a2 = __float_as_uint(ys[(m0 + g) * 132 + k + tg + 4]);
            const uint32_t a3 = __float_as_uint(ys[(m0 + g + 8) * 132 + k + tg + 4]);
#pragma unroll
            for (int nt = 0; nt < 4; ++nt) {
                const int col = n0 + nt * 8 + g;
                const uint32_t b0 = __float_as_uint(W2s[col * 132 + k + tg]);
                const uint32_t b1v = __float_as_uint(W2s[col * 132 + k + tg + 4]);
                mma8(acc[nt], a0, a1, a2, a3, b0, b1v);
            }
        }

        // (c) prefetch h for step t+1 (barrier-independent; overlaps RED drain)
        {
            const int tn = (t + 1 < T_STEPS) ? (t + 1) : t;
            const float* hn = g_h + (size_t)tn * BATCH * DIM;
#pragma unroll
            for (int j = 0; j < 8; ++j)
                hreg[j] = *(const float4*)&hn[(rb0 + j) * DIM + kbase + lane * 4];
        }

        // (d) accumulate partials into next pre buffer (no-return vector RED)
#pragma unroll
        for (int nt = 0; nt < 4; ++nt) {
            const int ccol = nbase + n0 + nt * 8 + tg * 2;
            red_add_v2(&nxt[(m0 + g) * DIM + ccol],     acc[nt][0], acc[nt][1]);
            red_add_v2(&nxt[(m0 + g + 8) * DIM + ccol], acc[nt][2], acc[nt][3]);
        }

        // (e) folded output projection on own rows (nc==0 CTAs only)
        if (nc == 0) {
#pragma unroll
            for (int j = 0; j < 8; ++j) {
                const float4 yv = *(const float4*)&ys[(rb0 + j) * 132 + lane * 4];
                const float4 wv = *(const float4*)&Wcs[lane * 4];
                float s = yv.x * wv.x + yv.y * wv.y + yv.z * wv.z + yv.w * wv.w;
                s += __shfl_xor_sync(0xffffffffu, s, 16);
                s += __shfl_xor_sync(0xffffffffu, s, 8);
                s += __shfl_xor_sync(0xffffffffu, s, 4);
                s += __shfl_xor_sync(0xffffffffu, s, 2);
                s += __shfl_xor_sync(0xffffffffu, s, 1);
                if (lane == 0) g_outp[t * (KC_N * BATCH) + kc * BATCH + rb0 + j] = s;
            }
        }

        // (f) zero the buffer that becomes the accumulation target at step t+1
        if (tid < 128)
            ((float4*)zb)[cid * 128 + tid] = make_float4(0.f, 0.f, 0.f, 0.f);

        // (g) grid barrier (monotonic counter; all 128 CTAs resident)
        __threadfence();
        __syncthreads();
        if (tid == 0) {
            atomicAdd(&g_bar, 1u);
            const unsigned target = (unsigned)(t + 1) * NCTA;
            while (*((volatile unsigned int*)&g_bar) < target) { }
            __threadfence();
        }
        __syncthreads();
    }

    // epilogue (folded final): out[b][t] = bc + sum_kc g_outp[t][kc][b]
    if (cid < 32) {
        const float bias = bc[0];
#pragma unroll
        for (int i = 0; i < 4; ++i) {
            const int idx = cid * 1024 + tid * 4 + i;   // 0..32767
            const int b = idx >> 9, tt = idx & 511;
            float s = bias;
#pragma unroll
            for (int k2 = 0; k2 < KC_N; k2++)
                s += g_outp[tt * (KC_N * BATCH) + k2 * BATCH + b];
            out[idx] = s;
        }
    }
}

// ---------------- launch ----------------
extern "C" void kernel_launch(void* const* d_in, const int* in_sizes, int n_in,
                              void* d_out, int out_size) {
    const float* X  = (const float*)d_in[0];
    const float* W1 = (const float*)d_in[1];
    const float* b1 = (const float*)d_in[2];
    const float* W2 = (const float*)d_in[3];
    const float* b2 = (const float*)d_in[4];
    const float* Wc = (const float*)d_in[5];
    const float* bc = (const float*)d_in[6];
    float* out = (float*)d_out;

    const int recur_smem = (64 * 132 + 64 * 132 + 128 + 128) * 4;  // 68608 B
    cudaFuncSetAttribute(recur_kernel, cudaFuncAttributeMaxDynamicSharedMemorySize, recur_smem);

    proj_kernel<<<dim3(8, 256), 256>>>(X, W1, b1);
    recur_kernel<<<NCTA, 256, recur_smem>>>(W2, b2, Wc, bc, out);
}

// round 7
// speedup vs baseline: 1.2913x; 1.1259x over previous
#include <cuda_runtime.h>
#include <cstdint>

// CustomRNN: B=64, T=512, D=U=1024
//   h = tanh(X @ W1 + b1)                      [parallel GEMM, tf32 mma]
//   y_t = h_t + tanh(y_{t-1} @ W2 + b2)        [512 sequential steps, persistent kernel]
//   out = y @ Wc + bc                          [folded into recurrence]

#define T_STEPS 512
#define BATCH   64
#define DIM     1024
#define NCTA    128     // recurrence grid: 8 K-chunks x 16 N-chunks, all resident
#define KC_N    8
#define KRANGE  128
#define NRANGE  64

// ---------------- device scratch (allocation-free contract) ----------------
__device__ float g_h[T_STEPS * BATCH * DIM];       // h[t][b][u], 134 MB
__device__ float g_pre[3][BATCH * DIM];            // rotating pre-activation buffers
__device__ float g_outp[T_STEPS * KC_N * BATCH];   // partial Wc dots [t][kc][b]
__device__ unsigned int g_bar;                     // monotonic grid barrier counter

// ---------------- helpers ----------------
__device__ __forceinline__ uint32_t f2tf_bits(float x) {
    uint32_t r;
    asm("cvt.rna.tf32.f32 %0, %1;" : "=r"(r) : "f"(x));
    return r;
}
__device__ __forceinline__ float f2tf(float x) { return __uint_as_float(f2tf_bits(x)); }

// tanh(x) = 1 - 2/(exp(2x)+1) via MUFU ex2/rcp. Rel err ~1e-6, saturates at +-1.
__device__ __forceinline__ float fast_tanh(float x) {
    float e, r;
    asm("ex2.approx.f32 %0, %1;" : "=f"(e) : "f"(x * 2.8853900817779268f));
    asm("rcp.approx.f32 %0, %1;" : "=f"(r) : "f"(e + 1.0f));
    return 1.0f - 2.0f * r;
}

// vectorized no-return global float2 reduction (sm_90+)
__device__ __forceinline__ void red_add_v2(float* p, float a, float b) {
    asm volatile("red.global.add.v2.f32 [%0], {%1, %2};"
                 :: "l"(p), "f"(a), "f"(b) : "memory");
}

// grid-barrier protocol: release-arrive / acquire-poll (no membars needed;
// bar.sync provides the intra-CTA happens-before edges)
__device__ __forceinline__ void bar_arrive_release(unsigned int* p) {
    asm volatile("red.release.gpu.global.add.u32 [%0], 1;" :: "l"(p) : "memory");
}
__device__ __forceinline__ unsigned int bar_load_acquire(unsigned int* p) {
    unsigned int v;
    asm volatile("ld.acquire.gpu.global.u32 %0, [%1];" : "=r"(v) : "l"(p) : "memory");
    return v;
}

__device__ __forceinline__ void mma8(float c[4], uint32_t a0, uint32_t a1, uint32_t a2, uint32_t a3,
                                     uint32_t b0, uint32_t b1) {
    asm volatile(
        "mma.sync.aligned.m16n8k8.row.col.f32.tf32.tf32.f32 "
        "{%0,%1,%2,%3},{%4,%5,%6,%7},{%8,%9},{%0,%1,%2,%3};\n"
        : "+f"(c[0]), "+f"(c[1]), "+f"(c[2]), "+f"(c[3])
        : "r"(a0), "r"(a1), "r"(a2), "r"(a3), "r"(b0), "r"(b1));
}

__device__ __forceinline__ void pair_bar(int id) {
    asm volatile("bar.sync %0, 64;" :: "r"(id) : "memory");
}

// ---------------- phase 1: h = tanh(X @ W1 + b1), tf32 mma -----------------
// M=32768 (b*512+t), N=1024, K=1024. 128x128 tile, BK=16, 256 threads (8 warps 2x4).
// Also performs per-run init (zero pre buffers + barrier counter).
__global__ __launch_bounds__(256) void proj_kernel(const float* __restrict__ X,
                                                   const float* __restrict__ W1,
                                                   const float* __restrict__ b1) {
    __shared__ float As[2][128][20];   // [m][k] pad->20 : conflict-free frag loads
    __shared__ float Bs[2][16][136];   // [k][n] pad->136: conflict-free frag loads

    const int tid = threadIdx.x;
    // folded init: zero g_pre (3 buffers) + g_bar before recur launches
    {
        const int flat = (blockIdx.y * gridDim.x + blockIdx.x) * 256 + tid;
        if (flat < 3 * BATCH * DIM / 4)
            ((float4*)&g_pre[0][0])[flat] = make_float4(0.f, 0.f, 0.f, 0.f);
        if (flat == 0) g_bar = 0u;
    }

    const int lane = tid & 31, wid = tid >> 5;
    const int g = lane >> 2, tg = lane & 3;
    const int wm0 = (wid >> 2) * 64, wn0 = (wid & 3) * 32;
    const int mbase = blockIdx.y * 128, nbase = blockIdx.x * 128;

    const int a_row0 = tid >> 2;            // 0..63
    const int a_row1 = a_row0 + 64;         // 64..127
    const int a_kq = (tid & 3) * 4;
    const int b_row0 = tid >> 5;            // 0..7
    const int b_row1 = b_row0 + 8;          // 8..15
    const int b_nq = (tid & 31) * 4;

    float acc[4][4][4];
#pragma unroll
    for (int mt = 0; mt < 4; mt++)
#pragma unroll
        for (int nt = 0; nt < 4; nt++)
#pragma unroll
            for (int i = 0; i < 4; i++) acc[mt][nt][i] = 0.0f;

    // prologue: tile 0
    float4 ra0 = *(const float4*)&X[(mbase + a_row0) * DIM + a_kq];
    float4 ra1 = *(const float4*)&X[(mbase + a_row1) * DIM + a_kq];
    float4 rb0 = *(const float4*)&W1[b_row0 * DIM + nbase + b_nq];
    float4 rb1 = *(const float4*)&W1[b_row1 * DIM + nbase + b_nq];
    {
        float4 v;
        v.x = f2tf(ra0.x); v.y = f2tf(ra0.y); v.z = f2tf(ra0.z); v.w = f2tf(ra0.w);
        *(float4*)&As[0][a_row0][a_kq] = v;
        v.x = f2tf(ra1.x); v.y = f2tf(ra1.y); v.z = f2tf(ra1.z); v.w = f2tf(ra1.w);
        *(float4*)&As[0][a_row1][a_kq] = v;
        v.x = f2tf(rb0.x); v.y = f2tf(rb0.y); v.z = f2tf(rb0.z); v.w = f2tf(rb0.w);
        *(float4*)&Bs[0][b_row0][b_nq] = v;
        v.x = f2tf(rb1.x); v.y = f2tf(rb1.y); v.z = f2tf(rb1.z); v.w = f2tf(rb1.w);
        *(float4*)&Bs[0][b_row1][b_nq] = v;
    }
    __syncthreads();

    for (int it = 0; it < 64; ++it) {
        const int cur = it & 1;
        if (it + 1 < 64) {
            const int kk = (it + 1) * 16;
            ra0 = *(const float4*)&X[(mbase + a_row0) * DIM + kk + a_kq];
            ra1 = *(const float4*)&X[(mbase + a_row1) * DIM + kk + a_kq];
            rb0 = *(const float4*)&W1[(kk + b_row0) * DIM + nbase + b_nq];
            rb1 = *(const float4*)&W1[(kk + b_row1) * DIM + nbase + b_nq];
        }
#pragma unroll
        for (int ks = 0; ks < 2; ++ks) {
            const int k = ks * 8;
            uint32_t af[4][4], bf[4][2];
#pragma unroll
            for (int mt = 0; mt < 4; mt++) {
                const int r = wm0 + mt * 16 + g;
                af[mt][0] = __float_as_uint(As[cur][r][k + tg]);
                af[mt][1] = __float_as_uint(As[cur][r + 8][k + tg]);
                af[mt][2] = __float_as_uint(As[cur][r][k + tg + 4]);
                af[mt][3] = __float_as_uint(As[cur][r + 8][k + tg + 4]);
            }
#pragma unroll
            for (int nt = 0; nt < 4; nt++) {
                const int c = wn0 + nt * 8 + g;
                bf[nt][0] = __float_as_uint(Bs[cur][k + tg][c]);
                bf[nt][1] = __float_as_uint(Bs[cur][k + tg + 4][c]);
            }
#pragma unroll
            for (int mt = 0; mt < 4; mt++)
#pragma unroll
                for (int nt = 0; nt < 4; nt++)
                    mma8(acc[mt][nt], af[mt][0], af[mt][1], af[mt][2], af[mt][3],
                         bf[nt][0], bf[nt][1]);
        }
        __syncthreads();
        if (it + 1 < 64) {
            const int nxt = cur ^ 1;
            float4 v;
            v.x = f2tf(ra0.x); v.y = f2tf(ra0.y); v.z = f2tf(ra0.z); v.w = f2tf(ra0.w);
            *(float4*)&As[nxt][a_row0][a_kq] = v;
            v.x = f2tf(ra1.x); v.y = f2tf(ra1.y); v.z = f2tf(ra1.z); v.w = f2tf(ra1.w);
            *(float4*)&As[nxt][a_row1][a_kq] = v;
            v.x = f2tf(rb0.x); v.y = f2tf(rb0.y); v.z = f2tf(rb0.z); v.w = f2tf(rb0.w);
            *(float4*)&Bs[nxt][b_row0][b_nq] = v;
            v.x = f2tf(rb1.x); v.y = f2tf(rb1.y); v.z = f2tf(rb1.z); v.w = f2tf(rb1.w);
            *(float4*)&Bs[nxt][b_row1][b_nq] = v;
            __syncthreads();
        }
    }

    // epilogue: tanh + bias, write h[t][b][u]
#pragma unroll
    for (int nt = 0; nt < 4; nt++) {
        const int c = nbase + wn0 + nt * 8 + tg * 2;
        const float bb0 = b1[c], bb1 = b1[c + 1];
#pragma unroll
        for (int mt = 0; mt < 4; mt++) {
            const int r = mbase + wm0 + mt * 16 + g;
            {
                float2 v;
                v.x = fast_tanh(acc[mt][nt][0] + bb0);
                v.y = fast_tanh(acc[mt][nt][1] + bb1);
                const int t = r & 511, b = r >> 9;
                *(float2*)&g_h[(t * 64 + b) * DIM + c] = v;
            }
            {
                const int r2 = r + 8;
                float2 v;
                v.x = fast_tanh(acc[mt][nt][2] + bb0);
                v.y = fast_tanh(acc[mt][nt][3] + bb1);
                const int t = r2 & 511, b = r2 >> 9;
                *(float2*)&g_h[(t * 64 + b) * DIM + c] = v;
            }
        }
    }
}

// ---------------- phase 2: persistent recurrence ----------------
// Grid = 128 CTAs (kc 0..7, nc 0..15), 256 threads = 4 warp pairs.
// Per step: build own y rows -> pair bar -> 16x32 warp GEMM -> RED partials
// -> zero ring buffer -> Wc dot -> syncthreads -> RELEASE arrive
// -> prefetch h(t+1) inside poll window -> ACQUIRE poll -> syncthreads.
// No per-thread membars: bar.sync + release/acquire carry all ordering.
__global__ __launch_bounds__(256, 1) void recur_kernel(const float* __restrict__ W2,
                                                       const float* __restrict__ b2,
                                                       const float* __restrict__ Wc,
                                                       const float* __restrict__ bc,
                                                       float* __restrict__ out) {
    extern __shared__ float sm[];
    float* W2s = sm;                  // [64][132], n-major, tf32-rounded
    float* ys  = sm + 64 * 132;       // [64][132]
    float* b2s = ys + 64 * 132;       // [128]
    float* Wcs = b2s + 128;           // [128]

    const int tid = threadIdx.x, lane = tid & 31, wid = tid >> 5;
    const int g = lane >> 2, tg = lane & 3;
    const int pair = wid >> 1, sub = wid & 1;
    const int m0 = pair * 16, n0 = sub * 32;
    const int rb0 = pair * 16 + sub * 8;     // this warp builds rows rb0..rb0+7
    const int cid = blockIdx.x;
    const int kc = cid >> 4, nc = cid & 15;
    const int kbase = kc * KRANGE, nbase = nc * NRANGE;

    // W2 slice resident in smem for all 512 steps
    for (int i = tid; i < NRANGE * KRANGE; i += 256) {
        const int n = i & 63, k = i >> 6;
        W2s[n * 132 + k] = f2tf(W2[(kbase + k) * DIM + nbase + n]);
    }
    if (tid < 128) { b2s[tid] = b2[kbase + tid]; Wcs[tid] = Wc[kbase + tid]; }
    __syncthreads();

    // prologue: prefetch h rows for t=0 (row = batch index, cols = K slice)
    float4 hreg[8];
#pragma unroll
    for (int j = 0; j < 8; ++j)
        hreg[j] = *(const float4*)&g_h[(size_t)(rb0 + j) * DIM + kbase + lane * 4];

    for (int t = 0; t < T_STEPS; ++t) {
        const float* pre = g_pre[t % 3];
        float* nxt = g_pre[(t + 1) % 3];
        float* zb  = g_pre[(t + 2) % 3];

        // (a) build own 8 y rows: y = tf32(h + tanh(pre + b2))
        float4 preg[8];
#pragma unroll
        for (int j = 0; j < 8; ++j)
            preg[j] = *(const float4*)&pre[(rb0 + j) * DIM + kbase + lane * 4];
#pragma unroll
        for (int j = 0; j < 8; ++j) {
            float4 y;
            y.x = f2tf(hreg[j].x + fast_tanh(preg[j].x + b2s[lane * 4 + 0]));
            y.y = f2tf(hreg[j].y + fast_tanh(preg[j].y + b2s[lane * 4 + 1]));
            y.z = f2tf(hreg[j].z + fast_tanh(preg[j].z + b2s[lane * 4 + 2]));
            y.w = f2tf(hreg[j].w + fast_tanh(preg[j].w + b2s[lane * 4 + 3]));
            *(float4*)&ys[(rb0 + j) * 132 + lane * 4] = y;
        }
        pair_bar(pair + 1);   // sync the 2 warps sharing rows [m0, m0+16)

        // (b) GEMM: warp tile 16(M) x 32(N) x 128(K)
        float acc[4][4];
#pragma unroll
        for (int nt = 0; nt < 4; nt++)
#pragma unroll
            for (int i = 0; i < 4; i++) acc[nt][i] = 0.0f;

#pragma unroll
        for (int ks = 0; ks < 16; ++ks) {
            const int k = ks * 8;
            const uint32_t a0 = __float_as_uint(ys[(m0 + g) * 132 + k + tg]);
            const uint32_t a1 = __float_as_uint(ys[(m0 + g + 8) * 132 + k + tg]);
            const uint32_t a2 = __float_as_uint(ys[(m0 + g) * 132 + k + tg + 4]);
            const uint32_t a3 = __float_as_uint(ys[(m0 + g + 8) * 132 + k + tg + 4]);
#pragma unroll
            for (int nt = 0; nt < 4; ++nt) {
                const int col = n0 + nt * 8 + g;
                const uint32_t b0 = __float_as_uint(W2s[col * 132 + k + tg]);
                const uint32_t b1v = __float_as_uint(W2s[col * 132 + k + tg + 4]);
                mma8(acc[nt], a0, a1, a2, a3, b0, b1v);
            }
        }

        // (c) accumulate partials into next pre buffer (no-return vector RED)
#pragma unroll
        for (int nt = 0; nt < 4; ++nt) {
            const int ccol = nbase + n0 + nt * 8 + tg * 2;
            red_add_v2(&nxt[(m0 + g) * DIM + ccol],     acc[nt][0], acc[nt][1]);
            red_add_v2(&nxt[(m0 + g + 8) * DIM + ccol], acc[nt][2], acc[nt][3]);
        }

        // (d) zero the buffer that becomes the accumulation target at step t+1
        //     (must precede the release-arrive: consumers RED into it at t+1)
        if (tid < 128)
            ((float4*)zb)[cid * 128 + tid] = make_float4(0.f, 0.f, 0.f, 0.f);

        // (e) folded output projection on own rows (nc==0 CTAs only)
        //     (before arrive: epilogue readers sync via the last barrier)
        if (nc == 0) {
#pragma unroll
            for (int j = 0; j < 8; ++j) {
                const float4 yv = *(const float4*)&ys[(rb0 + j) * 132 + lane * 4];
                const float4 wv = *(const float4*)&Wcs[lane * 4];
                float s = yv.x * wv.x + yv.y * wv.y + yv.z * wv.z + yv.w * wv.w;
                s += __shfl_xor_sync(0xffffffffu, s, 16);
                s += __shfl_xor_sync(0xffffffffu, s, 8);
                s += __shfl_xor_sync(0xffffffffu, s, 4);
                s += __shfl_xor_sync(0xffffffffu, s, 2);
                s += __shfl_xor_sync(0xffffffffu, s, 1);
                if (lane == 0) g_outp[t * (KC_N * BATCH) + kc * BATCH + rb0 + j] = s;
            }
        }

        // (f) grid barrier: bar.sync gives intra-CTA HB to tid0; release-arrive
        __syncthreads();
        if (tid == 0) bar_arrive_release(&g_bar);

        // (g) prefetch h for step t+1 — immutable data, overlaps the poll window
        {
            const int tn = (t + 1 < T_STEPS) ? (t + 1) : t;
            const float* hn = g_h + (size_t)tn * BATCH * DIM;
#pragma unroll
            for (int j = 0; j < 8; ++j)
                hreg[j] = *(const float4*)&hn[(rb0 + j) * DIM + kbase + lane * 4];
        }

        // (h) acquire-poll until all 128 CTAs arrived; bar.sync spreads the acquire
        if (tid == 0) {
            const unsigned target = (unsigned)(t + 1) * NCTA;
            while (bar_load_acquire(&g_bar) < target) { }
        }
        __syncthreads();
    }

    // epilogue (folded final): out[b][t] = bc + sum_kc g_outp[t][kc][b]
    if (cid < 32) {
        const float bias = bc[0];
#pragma unroll
        for (int i = 0; i < 4; ++i) {
            const int idx = cid * 1024 + tid * 4 + i;   // 0..32767
            const int b = idx >> 9, tt = idx & 511;
            float s = bias;
#pragma unroll
            for (int k2 = 0; k2 < KC_N; k2++)
                s += g_outp[tt * (KC_N * BATCH) + k2 * BATCH + b];
            out[idx] = s;
        }
    }
}

// ---------------- launch ----------------
extern "C" void kernel_launch(void* const* d_in, const int* in_sizes, int n_in,
                              void* d_out, int out_size) {
    const float* X  = (const float*)d_in[0];
    const float* W1 = (const float*)d_in[1];
    const float* b1 = (const float*)d_in[2];
    const float* W2 = (const float*)d_in[3];
    const float* b2 = (const float*)d_in[4];
    const float* Wc = (const float*)d_in[5];
    const float* bc = (const float*)d_in[6];
    float* out = (float*)d_out;

    const int recur_smem = (64 * 132 + 64 * 132 + 128 + 128) * 4;  // 68608 B
    cudaFuncSetAttribute(recur_kernel, cudaFuncAttributeMaxDynamicSharedMemorySize, recur_smem);

    proj_kernel<<<dim3(8, 256), 256>>>(X, W1, b1);
    recur_kernel<<<NCTA, 256, recur_smem>>>(W2, b2, Wc, bc, out);
}